// round 15
// baseline (speedup 1.0000x reference)
#include <cuda_runtime.h>
#include <cuda_bf16.h>
#include <math.h>
#include <stdint.h>

#define D 256
#define HALF_D 128
#define MAXN 4096
#define CAP 64         // CSR slots per row
#define HCAP 20        // CSR entries per (row, half) thread
#define TILE_M 64
#define TILE_N 128

// ---- device scratch (module-load zero-initialized; no allocations) ----
__device__ __align__(16) float2 g_cs[MAXN*HALF_D]; // (cos,sin) per (position, freq-pair)
__device__ float2 g_csr[D*CAP];                    // per-row edges (.x=col bits, .y=+/-val)
__device__ int    g_degh[D];                       // deg/2 per row
__device__ __align__(16) __nv_bfloat16 g_Bt[D*D];  // B^T: [n][k] = bf16(2*P[k][n]), P = Sum M^1..8

// bf16 HMMA, baseline PTX (sm_80+), fp32 accumulate in registers
__device__ __forceinline__ void mma16816(float* c, const uint4 a, const uint2 b) {
    asm volatile(
        "mma.sync.aligned.m16n8k16.row.col.f32.bf16.bf16.f32 "
        "{%0,%1,%2,%3}, {%4,%5,%6,%7}, {%8,%9}, {%0,%1,%2,%3};"
        : "+f"(c[0]), "+f"(c[1]), "+f"(c[2]), "+f"(c[3])
        : "r"(a.x), "r"(a.y), "r"(a.z), "r"(a.w), "r"(b.x), "r"(b.y));
}

// ---------------- CSR build v4: block-per-row, all chunks preloaded (MLP), prefix scan ----------------
// 256 blocks (one per row) x 256 threads. All chunk (r,c) loaded to registers upfront,
// then barrier/prefix chain runs with no exposed LDG latency. Order = edge order.
__global__ void __launch_bounds__(256) k_build(const int* __restrict__ rows,
                                               const int* __restrict__ cols,
                                               const float* __restrict__ sp, int E) {
    __shared__ int warpsum[8];
    const int row  = blockIdx.x;
    const int t    = threadIdx.x;
    const int lane = t & 31, wid = t >> 5;
    const int nch  = (E + 255) >> 8;    // <= 8 assumed (E <= 2048)

    int rr[8], cc[8];
    #pragma unroll
    for (int ch = 0; ch < 8; ch++) {
        int e = ch*256 + t;
        bool v = (ch < nch) && (e < E);
        rr[ch] = v ? rows[e] : -1;
        cc[ch] = v ? cols[e] : -1;
    }

    int running = 0;
    #pragma unroll
    for (int ch = 0; ch < 8; ch++) {
        if (ch >= nch) break;
        bool isr = (rr[ch] == row);
        bool hit = isr || (cc[ch] == row);
        unsigned mask = __ballot_sync(0xFFFFFFFFu, hit);
        if (lane == 0) warpsum[wid] = __popc(mask);
        __syncthreads();
        int base = running, tot = 0;
        #pragma unroll
        for (int w = 0; w < 8; w++) {
            int ws = warpsum[w];
            if (w < wid) base += ws;
            tot += ws;
        }
        running += tot;
        if (hit) {
            float v = sp[ch*256 + t];
            int pos = base + __popc(mask & ((1u << lane) - 1u));
            g_csr[row*CAP + pos] =
                make_float2(__int_as_float(isr ? cc[ch] : rr[ch]), isr ? v : -v);
        }
        __syncthreads();   // warpsum reused next chunk
    }
    if (t == 0) g_degh[row] = running >> 1;
}

// ---------------- fused prep: 4 B^T-columns per block (float4 Horner) + cos/sin table ----------------
// Blocks [0, 64): block b computes 2*P[:, 4b..4b+3] via 8 sparse Horner steps.
// Blocks [64, ...): cos/sin table entries.
__global__ void __launch_bounds__(512) k_prep(
        const int* __restrict__ pos, const float* __restrict__ freqs, int N) {
    int bx = blockIdx.x;
    int t  = threadIdx.x;

    if (bx >= 64) {
        int idx = (bx - 64) * 512 + t;
        int tableN = N * HALF_D;
        if (idx < tableN) {
            int n = idx >> 7, j = idx & (HALF_D - 1);
            float ang = (float)pos[n] * freqs[j];       // fp32 rounding matches ref
            const float INV2PI = 0.15915494309189535f;
            const float C1 = 6.2831854820251465f;
            const float C2 = -1.7484556000744263e-7f;
            float qf = rintf(ang * INV2PI);
            float r  = fmaf(-qf, C1, ang);
            r = fmaf(-qf, C2, r);
            g_cs[idx] = make_float2(__cosf(r), __sinf(r));
        }
        return;
    }

    __shared__ __align__(16) float4 u4[D];
    __shared__ __align__(16) float4 yp4[512];

    const int row = t & 255, h = t >> 8;
    const int j0 = bx * 4;
    const int d0 = g_degh[row];
    const int base = row * CAP + (h ? d0 : 0);

    // Half 0 owns entries [0, d0); half 1 owns [d0, deg). Tail slots beyond deg are
    // zero (FMA adds 0); half 0 masks i >= d0 (those slots hold half-1 data).
    float vv[HCAP]; int cc[HCAP];
    #pragma unroll
    for (int i = 0; i < HCAP; i++) {
        float2 e = g_csr[base + i];
        float v = e.y;
        if (h == 0 && i >= d0) v = 0.f;
        vv[i] = v;
        cc[i] = __float_as_int(e.x) & 255;
    }

    float4 s = make_float4(0.f, 0.f, 0.f, 0.f);
    #pragma unroll 1
    for (int it = 0; it < 8; it++) {
        if (h == 0) {
            float4 uu = s;
            if (row == j0    ) uu.x += 1.f;
            if (row == j0 + 1) uu.y += 1.f;
            if (row == j0 + 2) uu.z += 1.f;
            if (row == j0 + 3) uu.w += 1.f;
            u4[row] = uu;
        }
        __syncthreads();
        float4 part = make_float4(0.f, 0.f, 0.f, 0.f);
        #pragma unroll
        for (int i = 0; i < HCAP; i++) {
            float4 uv = u4[cc[i]];
            part.x = fmaf(vv[i], uv.x, part.x);
            part.y = fmaf(vv[i], uv.y, part.y);
            part.z = fmaf(vv[i], uv.z, part.z);
            part.w = fmaf(vv[i], uv.w, part.w);
        }
        yp4[t] = part;
        __syncthreads();
        if (h == 0) {
            float4 a = yp4[row], b = yp4[row + 256];
            s = make_float4(a.x + b.x, a.y + b.y, a.z + b.z, a.w + b.w);
        }
    }
    if (h == 0) {
        float sv[4] = {s.x, s.y, s.z, s.w};
        #pragma unroll
        for (int c = 0; c < 4; c++) {
            // B = 2*P, NO identity (added exactly in k_mma epilogue)
            g_Bt[(j0 + c)*D + row] = __float2bfloat16(2.f * sv[c]);
        }
    }
}

// ---------------- main GEMM via HMMA: out = H_rope + (Ahi+Alo)*B,  B = 2P (bf16) ----------------
// 64x128 tile, 256 threads = 8 warps (4 x 2), warp tile 16(M) x 64(N), K chunks of 64.
// A/B staged in smem directly in m16n8k16 fragment order:
//   A element (m, k):  f=m>>4, s=k>>4, lane=(m&7)*4+((k&7)>>1), reg=((m>>3)&1)+2*((k>>3)&1)
//   B element (k, n): nf=n>>3, s=k>>4, lane=(n&7)*4+((k&7)>>1), reg=(k>>3)&1
__global__ void __launch_bounds__(256) k_mma(const float* __restrict__ q,
                                             const float* __restrict__ kk,
                                             float* __restrict__ out,
                                             int BN, int N) {
    __shared__ uint32_t sAhi[2048];   // 64 x 64 bf16 (fragment order)
    __shared__ uint32_t sAlo[2048];
    __shared__ uint32_t sBhi[4096];   // 128 x 64 bf16 (fragment order)

    const int t = threadIdx.x, lane = t & 31, wid = t >> 5;
    const int wr = wid >> 1, wc = wid & 1;     // wr: 0..3 (16 rows each), wc: 0..1 (64 cols)
    const int row0 = blockIdx.x * TILE_M;
    const int col0 = blockIdx.y * TILE_N;

    const float* src; int rb;
    if (row0 < BN) { src = q; rb = row0; } else { src = kk; rb = row0 - BN; }
    const int nb = rb % N;   // tile never crosses batch boundary (N multiple of 64)

    float acc[8][4];
    #pragma unroll
    for (int b2 = 0; b2 < 8; b2++)
        #pragma unroll
        for (int e = 0; e < 4; e++) acc[b2][e] = 0.f;

    const uint32_t* B32 = (const uint32_t*)g_Bt;

    for (int ch = 0; ch < 4; ch++) {
        // ---- stage A chunk (64 rows x 64 k) with RoPE + hi/lo split (8 u32 pairs/thread) ----
        #pragma unroll
        for (int i = 0; i < 8; i++) {
            int idx = i*256 + t;
            int m = idx >> 5, pj = idx & 31;     // local k-pair pj -> k = 2*pj
            int jp = ch*32 + pj;                 // global rotation pair
            float2 v  = *(const float2*)(src + (size_t)(rb + m)*D + 2*jp);
            float2 cs = g_cs[(size_t)(nb + m)*HALF_D + jp];
            float e = v.x*cs.x - v.y*cs.y;
            float o = v.x*cs.y + v.y*cs.x;
            __nv_bfloat16 he = __float2bfloat16(e), ho = __float2bfloat16(o);
            uint32_t hp = ((uint32_t)__bfloat16_as_ushort(ho) << 16) | __bfloat16_as_ushort(he);
            float le = e - __bfloat162float(he), lo = o - __bfloat162float(ho);
            __nv_bfloat16 ge = __float2bfloat16(le), go = __float2bfloat16(lo);
            uint32_t lp = ((uint32_t)__bfloat16_as_ushort(go) << 16) | __bfloat16_as_ushort(ge);
            int addr = ((((m>>4)*4 + (pj>>3))*32 + (m&7)*4 + (pj&3)) << 2)
                     + ((m>>3)&1) + 2*((pj>>2)&1);
            sAhi[addr] = hp;
            sAlo[addr] = lp;
        }
        // ---- stage B chunk from precomputed B^T (16 u32 per thread) ----
        #pragma unroll
        for (int i = 0; i < 16; i++) {
            int idx = i*256 + t;
            int n = idx >> 5, pj = idx & 31;
            int gidx = (col0 + n)*(D/2) + ch*32 + pj;   // u32 index into [n][k] bf16
            uint32_t vh = B32[gidx];
            int addr = ((((n>>3)*4 + (pj>>3))*32 + (n&7)*4 + (pj&3)) << 1)
                     + ((pj>>2)&1);
            sBhi[addr] = vh;
        }
        __syncthreads();

        // ---- compute: 4 k16-steps, 2 passes (hi, lo) ----
        #pragma unroll
        for (int s = 0; s < 4; s++) {
            uint4 ah = ((const uint4*)sAhi)[(wr*4 + s)*32 + lane];
            uint4 al = ((const uint4*)sAlo)[(wr*4 + s)*32 + lane];
            #pragma unroll
            for (int b2 = 0; b2 < 8; b2++) {
                uint2 bh = ((const uint2*)sBhi)[((wc*8 + b2)*4 + s)*32 + lane];
                mma16816(acc[b2], ah, bh);
                mma16816(acc[b2], al, bh);
            }
        }
        __syncthreads();
    }

    // ---- epilogue: out = RoPE(H) (exact fp32, recomputed) + correction ----
    const int g  = lane >> 2, tq = lane & 3;
    const int mloc0 = wr*16 + g;
    #pragma unroll
    for (int b2 = 0; b2 < 8; b2++) {
        int n0 = col0 + (wc*8 + b2)*8 + tq*2;   // even: a full rotation pair
        int jn = n0 >> 1;
        #pragma unroll
        for (int rh = 0; rh < 2; rh++) {
            int mloc = mloc0 + rh*8;
            float2 v  = *(const float2*)(src + (size_t)(rb + mloc)*D + n0);
            float2 cs = g_cs[(size_t)(nb + mloc)*HALF_D + jn];
            float e = v.x*cs.x - v.y*cs.y;
            float o = v.x*cs.y + v.y*cs.x;
            *(float2*)&out[(size_t)(row0 + mloc)*D + n0] =
                make_float2(e + acc[b2][rh*2], o + acc[b2][rh*2 + 1]);
        }
    }
}

// ---------------- launcher: 3 launches total ----------------
extern "C" void kernel_launch(void* const* d_in, const int* in_sizes, int n_in,
                              void* d_out, int out_size) {
    const float* q     = (const float*)d_in[0];
    const float* k     = (const float*)d_in[1];
    const float* freqs = (const float*)d_in[2];
    const float* sp    = (const float*)d_in[3];
    const int*   pos   = (const int*)  d_in[4];
    const int*   rows  = (const int*)  d_in[5];
    const int*   cols  = (const int*)  d_in[6];
    float* out = (float*)d_out;

    int E    = in_sizes[3];
    int N    = in_sizes[4];
    int BN   = in_sizes[0] / D;   // rows of q (= B*N)
    int ROWS = 2 * BN;

    k_build<<<D, 256>>>(rows, cols, sp, E);

    int tableBlocks = (N*HALF_D + 511)/512;
    k_prep<<<64 + tableBlocks, 512>>>(pos, freqs, N);

    dim3 grid(ROWS/TILE_M, D/TILE_N);
    k_mma<<<grid, 256>>>(q, k, out, BN, N);
}

// round 17
// speedup vs baseline: 1.3732x; 1.3732x over previous
#include <cuda_runtime.h>
#include <cuda_bf16.h>
#include <math.h>
#include <stdint.h>

#define D 256
#define HALF_D 128
#define MAXN 4096
#define CAP 64         // CSR slots per row
#define HCAP 20        // CSR entries per (row, half) thread
#define TILE_M 64
#define RSTRIDE 258    // sRope row stride in floats (even; %32=2 spreads banks)

// dynamic smem: sAhi(8KB) + sAlo(8KB) + sB(32KB) + sRope(64*258*4 = 66048B)
#define SMEM_BYTES (16384 + 32768 + 64*RSTRIDE*4)

// ---- device scratch (module-load zero-initialized; no allocations) ----
__device__ __align__(16) float2 g_cs[MAXN*HALF_D]; // (cos,sin) per (position, freq-pair)
__device__ float2 g_csr[D*CAP];                    // per-row edges (.x=col bits, .y=+/-val)
__device__ int    g_degh[D];                       // deg/2 per row
// B = 2P (P = Sum M^1..8), stored DIRECTLY in m16n8k16 fragment order:
// bf16 index = (ch*8192 + ((nf*4 + s)*32 + lane)*2 + reg)*2 + half
//   ch=k>>6, s=(k>>4)&3, reg=(k>>3)&1, half=k&1, nf=n>>3, lane=(n&7)*4+((k&7)>>1)
__device__ __align__(16) __nv_bfloat16 g_Bf[D*D];

// bf16 HMMA, baseline PTX (sm_80+), fp32 accumulate in registers
__device__ __forceinline__ void mma16816(float* c, const uint4 a, const uint2 b) {
    asm volatile(
        "mma.sync.aligned.m16n8k16.row.col.f32.bf16.bf16.f32 "
        "{%0,%1,%2,%3}, {%4,%5,%6,%7}, {%8,%9}, {%0,%1,%2,%3};"
        : "+f"(c[0]), "+f"(c[1]), "+f"(c[2]), "+f"(c[3])
        : "r"(a.x), "r"(a.y), "r"(a.z), "r"(a.w), "r"(b.x), "r"(b.y));
}

// ---------------- CSR build v4: block-per-row, all chunks preloaded (MLP), prefix scan ----------------
__global__ void __launch_bounds__(256) k_build(const int* __restrict__ rows,
                                               const int* __restrict__ cols,
                                               const float* __restrict__ sp, int E) {
    __shared__ int warpsum[8];
    const int row  = blockIdx.x;
    const int t    = threadIdx.x;
    const int lane = t & 31, wid = t >> 5;
    const int nch  = (E + 255) >> 8;

    int rr[8], cc[8];
    #pragma unroll
    for (int ch = 0; ch < 8; ch++) {
        int e = ch*256 + t;
        bool v = (ch < nch) && (e < E);
        rr[ch] = v ? rows[e] : -1;
        cc[ch] = v ? cols[e] : -1;
    }

    int running = 0;
    #pragma unroll
    for (int ch = 0; ch < 8; ch++) {
        if (ch >= nch) break;
        bool isr = (rr[ch] == row);
        bool hit = isr || (cc[ch] == row);
        unsigned mask = __ballot_sync(0xFFFFFFFFu, hit);
        if (lane == 0) warpsum[wid] = __popc(mask);
        __syncthreads();
        int base = running, tot = 0;
        #pragma unroll
        for (int w = 0; w < 8; w++) {
            int ws = warpsum[w];
            if (w < wid) base += ws;
            tot += ws;
        }
        running += tot;
        if (hit) {
            float v = sp[ch*256 + t];
            int pos = base + __popc(mask & ((1u << lane) - 1u));
            g_csr[row*CAP + pos] =
                make_float2(__int_as_float(isr ? cc[ch] : rr[ch]), isr ? v : -v);
        }
        __syncthreads();
    }
    if (t == 0) g_degh[row] = running >> 1;
}

// ---------------- fused prep: 4 B-columns per block (float4 Horner) + cos/sin table ----------------
// Writes B = 2P straight into fragment-order g_Bf.
__global__ void __launch_bounds__(512) k_prep(
        const int* __restrict__ pos, const float* __restrict__ freqs, int N) {
    int bx = blockIdx.x;
    int t  = threadIdx.x;

    if (bx >= 64) {
        int idx = (bx - 64) * 512 + t;
        int tableN = N * HALF_D;
        if (idx < tableN) {
            int n = idx >> 7, j = idx & (HALF_D - 1);
            float ang = (float)pos[n] * freqs[j];       // fp32 rounding matches ref
            const float INV2PI = 0.15915494309189535f;
            const float C1 = 6.2831854820251465f;
            const float C2 = -1.7484556000744263e-7f;
            float qf = rintf(ang * INV2PI);
            float r  = fmaf(-qf, C1, ang);
            r = fmaf(-qf, C2, r);
            g_cs[idx] = make_float2(__cosf(r), __sinf(r));
        }
        return;
    }

    __shared__ __align__(16) float4 u4[D];
    __shared__ __align__(16) float4 yp4[512];

    const int row = t & 255, h = t >> 8;
    const int j0 = bx * 4;
    const int d0 = g_degh[row];
    const int base = row * CAP + (h ? d0 : 0);

    float vv[HCAP]; int cc[HCAP];
    #pragma unroll
    for (int i = 0; i < HCAP; i++) {
        float2 e = g_csr[base + i];
        float v = e.y;
        if (h == 0 && i >= d0) v = 0.f;      // those slots hold half-1 data
        vv[i] = v;                            // half-1 tail slots are zero -> adds 0
        cc[i] = __float_as_int(e.x) & 255;
    }

    float4 s = make_float4(0.f, 0.f, 0.f, 0.f);
    #pragma unroll 1
    for (int it = 0; it < 8; it++) {
        if (h == 0) {
            float4 uu = s;
            if (row == j0    ) uu.x += 1.f;
            if (row == j0 + 1) uu.y += 1.f;
            if (row == j0 + 2) uu.z += 1.f;
            if (row == j0 + 3) uu.w += 1.f;
            u4[row] = uu;
        }
        __syncthreads();
        float4 part = make_float4(0.f, 0.f, 0.f, 0.f);
        #pragma unroll
        for (int i = 0; i < HCAP; i++) {
            float4 uv = u4[cc[i]];
            part.x = fmaf(vv[i], uv.x, part.x);
            part.y = fmaf(vv[i], uv.y, part.y);
            part.z = fmaf(vv[i], uv.z, part.z);
            part.w = fmaf(vv[i], uv.w, part.w);
        }
        yp4[t] = part;
        __syncthreads();
        if (h == 0) {
            float4 a = yp4[row], b = yp4[row + 256];
            s = make_float4(a.x + b.x, a.y + b.y, a.z + b.z, a.w + b.w);
        }
    }
    if (h == 0) {
        float sv[4] = {s.x, s.y, s.z, s.w};
        const int k   = row;
        const int chq = k >> 6, sq = (k >> 4) & 3, rq = (k >> 3) & 1, hf = k & 1;
        const int lof = (k & 7) >> 1;
        #pragma unroll
        for (int c = 0; c < 4; c++) {
            int n = j0 + c;
            int laneq = (n & 7) * 4 + lof;
            int u32idx = chq*8192 + (((n >> 3)*4 + sq)*32 + laneq)*2 + rq;
            g_Bf[u32idx*2 + hf] = __float2bfloat16(2.f * sv[c]);
        }
    }
}

// ---------------- main GEMM via HMMA: out = H_rope + (Ahi+Alo)*B ----------------
// 64x256 tile (FULL width), 256 threads = 8 warps (4 x 2), warp tile 16 x 128.
// One wave: 256 blocks @ 2 blocks/SM. B-stage = contiguous copy (fragment-order global).
// fp32 RoPE values kept in sRope; epilogue = acc-add (smem) + coalesced copy-out.
__global__ void __launch_bounds__(256, 2) k_mma(const float* __restrict__ q,
                                                const float* __restrict__ kk,
                                                float* __restrict__ out,
                                                int BN, int N) {
    extern __shared__ uint32_t sm[];
    uint32_t* sAhi = sm;             // 2048 u32
    uint32_t* sAlo = sm + 2048;      // 2048 u32
    uint32_t* sB   = sm + 4096;      // 8192 u32
    float*    sRope = (float*)(sm + 12288);  // 64 x RSTRIDE f32

    const int t = threadIdx.x, lane = t & 31, wid = t >> 5;
    const int wr = wid >> 1, wc = wid & 1;    // wr: rows-of-16, wc: n-half of 128
    const int row0 = blockIdx.x * TILE_M;

    const float* src; int rb;
    if (row0 < BN) { src = q; rb = row0; } else { src = kk; rb = row0 - BN; }
    const int nb = rb % N;   // tile never crosses batch boundary (N multiple of 64)

    float acc[16][4];
    #pragma unroll
    for (int b2 = 0; b2 < 16; b2++)
        #pragma unroll
        for (int e = 0; e < 4; e++) acc[b2][e] = 0.f;

    const uint4* Bf4 = (const uint4*)g_Bf;   // 2048 u4 per chunk

    for (int ch = 0; ch < 4; ch++) {
        // ---- stage A chunk (64 rows x 64 k): RoPE + hi/lo split + save fp32 to sRope ----
        #pragma unroll
        for (int i = 0; i < 8; i++) {
            int idx = i*256 + t;
            int m = idx >> 5, pj = idx & 31;     // k = 2*(ch*32+pj)
            int jp = ch*32 + pj;
            float2 v  = *(const float2*)(src + (size_t)(rb + m)*D + 2*jp);
            float2 cs = g_cs[(size_t)(nb + m)*HALF_D + jp];
            float e = v.x*cs.x - v.y*cs.y;
            float o = v.x*cs.y + v.y*cs.x;
            *(float2*)&sRope[m*RSTRIDE + 2*jp] = make_float2(e, o);
            __nv_bfloat16 he = __float2bfloat16(e), ho = __float2bfloat16(o);
            uint32_t hp = ((uint32_t)__bfloat16_as_ushort(ho) << 16) | __bfloat16_as_ushort(he);
            float le = e - __bfloat162float(he), lo = o - __bfloat162float(ho);
            __nv_bfloat16 ge = __float2bfloat16(le), go = __float2bfloat16(lo);
            uint32_t lp = ((uint32_t)__bfloat16_as_ushort(go) << 16) | __bfloat16_as_ushort(ge);
            int addr = ((((m>>4)*4 + (pj>>3))*32 + (m&7)*4 + (pj&3)) << 2)
                     + ((m>>3)&1) + 2*((pj>>2)&1);
            sAhi[addr] = hp;
            sAlo[addr] = lp;
        }
        // ---- stage B chunk: contiguous 32KB copy (already fragment-order) ----
        #pragma unroll
        for (int i = 0; i < 8; i++) {
            int idx = i*256 + t;
            ((uint4*)sB)[idx] = Bf4[ch*2048 + idx];
        }
        __syncthreads();

        // ---- compute: 4 k16-steps, 2 passes (hi, lo), 16 n-frags ----
        #pragma unroll
        for (int s = 0; s < 4; s++) {
            uint4 ah = ((const uint4*)sAhi)[(wr*4 + s)*32 + lane];
            uint4 al = ((const uint4*)sAlo)[(wr*4 + s)*32 + lane];
            #pragma unroll
            for (int b2 = 0; b2 < 16; b2++) {
                uint2 bh = ((const uint2*)sB)[(((wc*16 + b2)*4 + s)*32 + lane)];
                mma16816(acc[b2], ah, bh);
                mma16816(acc[b2], al, bh);
            }
        }
        __syncthreads();
    }

    // ---- epilogue phase 1: add correction into sRope (out = rope + corr) ----
    {
        const int g = lane >> 2, tq = lane & 3;
        #pragma unroll
        for (int b2 = 0; b2 < 16; b2++) {
            int n0 = wc*128 + b2*8 + tq*2;
            #pragma unroll
            for (int rh = 0; rh < 2; rh++) {
                int mloc = wr*16 + g + rh*8;
                float2* p = (float2*)&sRope[mloc*RSTRIDE + n0];
                float2 v = *p;
                v.x += acc[b2][rh*2];
                v.y += acc[b2][rh*2 + 1];
                *p = v;
            }
        }
    }
    __syncthreads();

    // ---- epilogue phase 2: coalesced copy-out (warp-per-row, float2) ----
    #pragma unroll
    for (int r8 = 0; r8 < 8; r8++) {
        int row = r8*8 + wid;
        const float* rp = &sRope[row*RSTRIDE];
        float* op = out + (size_t)(row0 + row)*D;
        #pragma unroll
        for (int cs2 = 0; cs2 < 4; cs2++) {
            int c = (cs2*32 + lane)*2;
            *(float2*)&op[c] = *(const float2*)&rp[c];
        }
    }
}

// ---------------- launcher: 3 launches total ----------------
extern "C" void kernel_launch(void* const* d_in, const int* in_sizes, int n_in,
                              void* d_out, int out_size) {
    const float* q     = (const float*)d_in[0];
    const float* k     = (const float*)d_in[1];
    const float* freqs = (const float*)d_in[2];
    const float* sp    = (const float*)d_in[3];
    const int*   pos   = (const int*)  d_in[4];
    const int*   rows  = (const int*)  d_in[5];
    const int*   cols  = (const int*)  d_in[6];
    float* out = (float*)d_out;

    int E    = in_sizes[3];
    int N    = in_sizes[4];
    int BN   = in_sizes[0] / D;   // rows of q (= B*N)
    int ROWS = 2 * BN;

    k_build<<<D, 256>>>(rows, cols, sp, E);

    int tableBlocks = (N*HALF_D + 511)/512;
    k_prep<<<64 + tableBlocks, 512>>>(pos, freqs, N);

    cudaFuncSetAttribute(k_mma, cudaFuncAttributeMaxDynamicSharedMemorySize, SMEM_BYTES);
    k_mma<<<ROWS/TILE_M, 256, SMEM_BYTES>>>(q, k, out, BN, N);
}